// round 12
// baseline (speedup 1.0000x reference)
#include <cuda_runtime.h>
#include <math.h>

// Problem constants (fixed by the reference setup_inputs)
#define NB 16
#define NA 5
#define NCLS 20
#define NH 64
#define NW 64
#define MAXGT 50
#define CH (NA * (5 + NCLS))       // 125
#define SPLANE (NH * NW)           // 4096
#define SIL_T 0.6f

#define TPB 640                    // threads per block (20 warps)
#define CELLBLK 8                  // cell blocks per batch (8*640 = 5120 units)
#define BXDIM (CELLBLK + 1)        // 9 (last column: GT-correction)
#define NBLOCKS (BXDIM * NB)       // 144  (<= 148 SMs: one balanced wave)
#define NWARPS (TPB / 32)          // 20

__device__ double   g_acc = 0.0;
__device__ unsigned g_counter = 0;

__device__ __forceinline__ float tanh_fast(float v) {
    float r;
    asm("tanh.approx.f32 %0, %1;" : "=f"(r) : "f"(v));
    return r;
}
// sigmoid(v) = 0.5*tanh(v/2) + 0.5   (1 MUFU + 2 FMA)
__device__ __forceinline__ float sigm_fast(float v) {
    return fmaf(0.5f, tanh_fast(0.5f * v), 0.5f);
}
__device__ __forceinline__ float sigm(float v) { return 1.0f / (1.0f + expf(-v)); }

__device__ __forceinline__ float iou_corners(float px1, float py1, float px2, float py2, float parea,
                                             float bx1, float by1, float bx2, float by2, float barea) {
    float iw = fmaxf(fminf(px2, bx2) - fmaxf(px1, bx1), 0.0f);
    float ih = fmaxf(fminf(py2, by2) - fmaxf(py1, by1), 0.0f);
    float inter = iw * ih;
    float uni = parea + barea - inter;
    return uni > 0.0f ? inter / uni : 0.0f;
}

__global__ __launch_bounds__(TPB, 1) void yolo_fused(const float* __restrict__ out,
                                                     const float* __restrict__ tgt,
                                                     const float* __restrict__ anc,
                                                     float* __restrict__ res) {
    __shared__ float4 sboxv[MAXGT];   // compacted GT corners x1,y1,x2,y2
    __shared__ float  sb6[MAXGT];     // 0.6 * area
    __shared__ int    scnt;
    __shared__ float  ssum[NWARPS];
    __shared__ int    sflat[MAXGT];

    const int b = blockIdx.y;
    const int bx = blockIdx.x;
    const int tid = threadIdx.x;
    const int lane = tid & 31;
    const int wid = tid >> 5;
    const bool cellBlock = (bx < CELLBLK);

    // ====== prefetch this thread's single unit (independent of tgt) ======
    float4 L0, L1, L2, L3, L4;
    float aw_ = 0.f, ah_ = 0.f;
    int j_ = 0, i0_ = 0;
    if (cellBlock) {
        int unit = bx * TPB + tid;       // 0..5119
        int a_ = unit >> 10;             // 1024 float4-units per anchor plane
        int rem = unit & 1023;
        j_ = rem >> 4;
        i0_ = (rem & 15) * 4;
        int base = ((b * CH + a_ * (5 + NCLS)) * NH + j_) * NW + i0_;
        L0 = *(const float4*)(out + base);
        L1 = *(const float4*)(out + base + SPLANE);
        L2 = *(const float4*)(out + base + 2 * SPLANE);
        L3 = *(const float4*)(out + base + 3 * SPLANE);
        L4 = *(const float4*)(out + base + 4 * SPLANE);
        aw_ = __ldg(&anc[2 * a_]);
        ah_ = __ldg(&anc[2 * a_ + 1]);
    }

    // ====== GT preprocessing: warp 0 only, ONE barrier ======
    if (wid == 0) {
        const float* tb = tgt + b * MAXGT * 5;
        float a1 = tb[lane * 5 + 1];
        float a2 = tb[lane * 5 + 2];
        float a3 = tb[lane * 5 + 3];
        float a4 = tb[lane * 5 + 4];
        bool vA = (a1 > 0.0f);
        float c1 = 0.f, c2 = 0.f, c3 = 0.f, c4 = 0.f;
        bool vB = false;
        if (lane < MAXGT - 32) {
            int s = 32 + lane;
            c1 = tb[s * 5 + 1]; c2 = tb[s * 5 + 2];
            c3 = tb[s * 5 + 3]; c4 = tb[s * 5 + 4];
            vB = (c1 > 0.0f);
        }
        unsigned mA = __ballot_sync(0xffffffffu, vA);
        unsigned mB = __ballot_sync(0xffffffffu, vB);
        int cA = __popc(mA);
        if (vA) {
            int idx = __popc(mA & ((1u << lane) - 1u));
            float gx = a1 * NW, gy = a2 * NH, gw = a3 * NW, gh = a4 * NH;
            sboxv[idx] = make_float4(gx - gw * 0.5f, gy - gh * 0.5f,
                                     gx + gw * 0.5f, gy + gh * 0.5f);
            sb6[idx] = SIL_T * (gw * gh);
        }
        if (vB) {
            int idx = cA + __popc(mB & ((1u << lane) - 1u));
            float gx = c1 * NW, gy = c2 * NH, gw = c3 * NW, gh = c4 * NH;
            sboxv[idx] = make_float4(gx - gw * 0.5f, gy - gh * 0.5f,
                                     gx + gw * 0.5f, gy + gh * 0.5f);
            sb6[idx] = SIL_T * (gw * gh);
        }
        if (lane == 0) scnt = cA + __popc(mB);
    }
    __syncthreads();
    const int cnt = scnt;

    float local = 0.0f;

    if (cellBlock) {
        const float fj = (float)j_;

        float xs[4] = {sigm_fast(L0.x), sigm_fast(L0.y), sigm_fast(L0.z), sigm_fast(L0.w)};
        float ys[4] = {sigm_fast(L1.x), sigm_fast(L1.y), sigm_fast(L1.z), sigm_fast(L1.w)};
        float ws[4] = {L2.x, L2.y, L2.z, L2.w};
        float hs[4] = {L3.x, L3.y, L3.z, L3.w};
        float cs[4] = {sigm_fast(L4.x), sigm_fast(L4.y), sigm_fast(L4.z), sigm_fast(L4.w)};

        float px1[4], py1[4], px2[4], py2[4], p6[4], mi[4];
        #pragma unroll
        for (int c = 0; c < 4; ++c) {
            float px = xs[c] + (float)(i0_ + c);
            float py = ys[c] + fj;
            float pw = __expf(ws[c]) * aw_;
            float ph = __expf(hs[c]) * ah_;
            px1[c] = px - pw * 0.5f; py1[c] = py - ph * 0.5f;
            px2[c] = px + pw * 0.5f; py2[c] = py + ph * 0.5f;
            p6[c]  = SIL_T * (pw * ph);
            mi[c]  = -1e30f;          // running max of 1.6*inter - 0.6*barea
        }

        // ---- warp-uniform y-interval for culling GT boxes ----
        // A GT box with no y-overlap contributes (−b6) < 0 < p6 to mi:
        // provably a no-op, so the whole warp may skip it.
        float wymin = fminf(fminf(py1[0], py1[1]), fminf(py1[2], py1[3]));
        float wymax = fmaxf(fmaxf(py2[0], py2[1]), fmaxf(py2[2], py2[3]));
        #pragma unroll
        for (int off = 16; off > 0; off >>= 1) {
            wymin = fminf(wymin, __shfl_xor_sync(0xffffffffu, wymin, off));
            wymax = fmaxf(wymax, __shfl_xor_sync(0xffffffffu, wymax, off));
        }

        for (int g = 0; g < cnt; ++g) {
            float4 bv = sboxv[g];
            if (bv.w < wymin || bv.y > wymax) continue;   // warp-uniform skip
            float b6 = sb6[g];
            #pragma unroll
            for (int c = 0; c < 4; ++c) {
                float iw = fmaxf(fminf(px2[c], bv.z) - fmaxf(px1[c], bv.x), 0.0f);
                float ih = fmaxf(fminf(py2[c], bv.w) - fmaxf(py1[c], bv.y), 0.0f);
                // max_iou > 0.6 <=> max_g(1.6*inter - 0.6*barea) > 0.6*parea
                mi[c] = fmaxf(mi[c], fmaf((1.0f + SIL_T), iw * ih, -b6));
            }
        }

        #pragma unroll
        for (int c = 0; c < 4; ++c) {
            float dx = xs[c] - 0.5f, dy = ys[c] - 0.5f;
            float cmb = (mi[c] > p6[c]) ? 0.0f : 1.0f;
            local += 0.5f * (dx * dx + dy * dy + ws[c] * ws[c] + hs[c] * hs[c])
                   + 0.5f * cmb * cs[c] * cs[c];
        }
    } else {
        // ---- per-GT correction terms (one thread per GT slot) ----
        int best = 0;
        float txv = 0.f, tyv = 0.f, twv = 0.f, thv = 0.f;
        int tcls = 0;
        bool valid = false;
        float gx = 0.f, gy = 0.f, gw = 0.f, gh = 0.f;

        if (tid < MAXGT) {
            const float* t = tgt + (b * MAXGT + tid) * 5;
            float t0 = t[0], t1 = t[1], t2 = t[2], t3 = t[3], t4 = t[4];
            valid = (t1 > 0.0f);
            if (valid) {
                gx = t1 * NW; gy = t2 * NH; gw = t3 * NW; gh = t4 * NH;
                float bestiou = -1.0f;
                for (int a = 0; a < NA; ++a) {
                    float aw = __ldg(&anc[2 * a]), ah = __ldg(&anc[2 * a + 1]);
                    float inter = fminf(gw, aw) * fminf(gh, ah);
                    float uni = gw * gh + aw * ah - inter;
                    float io = uni > 0.0f ? inter / uni : 0.0f;
                    if (io > bestiou) { bestiou = io; best = a; }
                }
                int gi = min(max((int)gx, 0), NW - 1);
                int gj = min(max((int)gy, 0), NH - 1);
                sflat[tid] = ((b * NA + best) * NH + gj) * NW + gi;
                float aw = __ldg(&anc[2 * best]), ah = __ldg(&anc[2 * best + 1]);
                txv = gx - (float)gi;
                tyv = gy - (float)gj;
                twv = logf(fmaxf(gw, 1e-12f) / aw);
                thv = logf(fmaxf(gh, 1e-12f) / ah);
                tcls = (int)t0;
            } else {
                sflat[tid] = -1;
            }
        }
        __syncthreads();   // GT block only: sflat visibility across warps

        if (tid < MAXGT && valid) {
            // last-write-wins: skip if a later valid GT writes the same cell
            bool skip = false;
            int myflat = sflat[tid];
            for (int g2 = tid + 1; g2 < MAXGT; ++g2)
                if (sflat[g2] == myflat) skip = true;

            if (!skip) {
                int i = myflat & 63;
                int j = (myflat >> 6) & 63;
                int a = best;
                int base = ((b * CH + a * (5 + NCLS)) * NH + j) * NW + i;

                float o0 = out[base];
                float o1 = out[base + SPLANE];
                float o2 = out[base + 2 * SPLANE];
                float o3 = out[base + 3 * SPLANE];
                float o4 = out[base + 4 * SPLANE];
                float x = sigm(o0), y = sigm(o1), w = o2, h = o3, conf = sigm(o4);

                float aw = __ldg(&anc[2 * a]), ah = __ldg(&anc[2 * a + 1]);
                float px = x + (float)i, py = y + (float)j;
                float pw = expf(w) * aw, ph = expf(h) * ah;
                float px1 = px - pw * 0.5f, py1 = py - ph * 0.5f;
                float px2 = px + pw * 0.5f, py2 = py + ph * 0.5f;
                float parea = pw * ph;
                float p6 = SIL_T * parea;

                bool over = false;
                for (int g = 0; g < cnt; ++g) {
                    float4 bv = sboxv[g];
                    float iw = fmaxf(fminf(px2, bv.z) - fmaxf(px1, bv.x), 0.0f);
                    float ih = fmaxf(fminf(py2, bv.w) - fmaxf(py1, bv.y), 0.0f);
                    over |= (1.0f + SIL_T) * (iw * ih) > (p6 + sb6[g]);
                }
                float cmb = over ? 0.0f : 1.0f;

                // iou of predicted box at this cell vs THIS gt box (precise)
                float iou_best = iou_corners(px1, py1, px2, py2, parea,
                                             gx - gw * 0.5f, gy - gh * 0.5f,
                                             gx + gw * 0.5f, gy + gh * 0.5f, gw * gh);

                float d = 0.0f, e;
                e = x - txv;       d += 0.5f * e * e;
                e = x - 0.5f;      d -= 0.5f * e * e;
                e = y - tyv;       d += 0.5f * e * e;
                e = y - 0.5f;      d -= 0.5f * e * e;
                e = w - twv;       d += 0.5f * e * e;  d -= 0.5f * w * w;
                e = h - thv;       d += 0.5f * e * e;  d -= 0.5f * h * h;
                e = conf - iou_best; d += 0.5f * 5.0f * e * e;
                d -= 0.5f * cmb * conf * conf;

                // class NLL
                float mx = -1e30f;
                #pragma unroll
                for (int c = 0; c < NCLS; ++c)
                    mx = fmaxf(mx, out[base + (5 + c) * SPLANE]);
                float s = 0.0f;
                #pragma unroll
                for (int c = 0; c < NCLS; ++c)
                    s += expf(out[base + (5 + c) * SPLANE] - mx);
                d += mx + logf(s) - out[base + (5 + tcls) * SPLANE];

                local = d;
            }
        }
    }

    // ---- block reduction (float), then ONE double atomic per block ----
    for (int off = 16; off > 0; off >>= 1)
        local += __shfl_down_sync(0xffffffffu, local, off);
    if (lane == 0) ssum[wid] = local;
    __syncthreads();
    if (tid == 0) {
        float v = ssum[0];
        #pragma unroll
        for (int k = 1; k < NWARPS; ++k) v += ssum[k];
        atomicAdd(&g_acc, (double)v);
        __threadfence();
        unsigned c = atomicAdd(&g_counter, 1u);
        if (c == NBLOCKS - 1) {
            __threadfence();
            double total = *((volatile double*)&g_acc);
            res[0] = (float)total;
            g_acc = 0.0;        // reset for next graph replay
            g_counter = 0;
        }
    }
}

extern "C" void kernel_launch(void* const* d_in, const int* in_sizes, int n_in,
                              void* d_out, int out_size) {
    const float* out = (const float*)d_in[0];
    const float* tgt = (const float*)d_in[1];
    const float* anc = (const float*)d_in[2];

    dim3 grid(BXDIM, NB);
    yolo_fused<<<grid, TPB>>>(out, tgt, anc, (float*)d_out);
}

// round 13
// speedup vs baseline: 1.0299x; 1.0299x over previous
#include <cuda_runtime.h>
#include <math.h>

// Problem constants (fixed by the reference setup_inputs)
#define NB 16
#define NA 5
#define NCLS 20
#define NH 64
#define NW 64
#define MAXGT 50
#define CH (NA * (5 + NCLS))       // 125
#define SPLANE (NH * NW)           // 4096
#define SIL_T 0.6f

#define TPB 640                    // threads per block (20 warps)
#define CELLBLK 8                  // cell blocks per batch (8*640 = 5120 units)
#define BXDIM (CELLBLK + 1)        // 9 (last column: GT-correction)
#define NBLOCKS (BXDIM * NB)       // 144  (<= 148 SMs: one balanced wave)
#define NWARPS (TPB / 32)          // 20
#define NSLOT 16

__device__ double   g_slot[NSLOT];   // zero-initialized at load; reset each run
__device__ unsigned g_counter = 0;

__device__ __forceinline__ float tanh_fast(float v) {
    float r;
    asm("tanh.approx.f32 %0, %1;" : "=f"(r) : "f"(v));
    return r;
}
// sigmoid(v) = 0.5*tanh(v/2) + 0.5   (1 MUFU + 2 FMA)
__device__ __forceinline__ float sigm_fast(float v) {
    return fmaf(0.5f, tanh_fast(0.5f * v), 0.5f);
}
__device__ __forceinline__ float sigm(float v) { return 1.0f / (1.0f + expf(-v)); }

__device__ __forceinline__ float iou_corners(float px1, float py1, float px2, float py2, float parea,
                                             float bx1, float by1, float bx2, float by2, float barea) {
    float iw = fmaxf(fminf(px2, bx2) - fmaxf(px1, bx1), 0.0f);
    float ih = fmaxf(fminf(py2, by2) - fmaxf(py1, by1), 0.0f);
    float inter = iw * ih;
    float uni = parea + barea - inter;
    return uni > 0.0f ? inter / uni : 0.0f;
}

__global__ __launch_bounds__(TPB, 1) void yolo_fused(const float* __restrict__ out,
                                                     const float* __restrict__ tgt,
                                                     const float* __restrict__ anc,
                                                     float* __restrict__ res) {
    __shared__ float4 sboxv[MAXGT];   // compacted GT corners x1,y1,x2,y2
    __shared__ float  sb6[MAXGT];     // 0.6 * area
    __shared__ int    scnt;
    __shared__ float  ssum[NWARPS];
    __shared__ int    sflat[MAXGT];

    const int b = blockIdx.y;
    const int bx = blockIdx.x;
    const int tid = threadIdx.x;
    const int lane = tid & 31;
    const int wid = tid >> 5;
    const bool cellBlock = (bx < CELLBLK);

    // ====== prefetch this thread's single unit (independent of tgt) ======
    float4 L0, L1, L2, L3, L4;
    float aw_ = 0.f, ah_ = 0.f;
    int j_ = 0, i0_ = 0;
    if (cellBlock) {
        int unit = bx * TPB + tid;       // 0..5119
        int a_ = unit >> 10;             // 1024 float4-units per anchor plane
        int rem = unit & 1023;
        j_ = rem >> 4;
        i0_ = (rem & 15) * 4;
        int base = ((b * CH + a_ * (5 + NCLS)) * NH + j_) * NW + i0_;
        L0 = *(const float4*)(out + base);
        L1 = *(const float4*)(out + base + SPLANE);
        L2 = *(const float4*)(out + base + 2 * SPLANE);
        L3 = *(const float4*)(out + base + 3 * SPLANE);
        L4 = *(const float4*)(out + base + 4 * SPLANE);
        aw_ = __ldg(&anc[2 * a_]);
        ah_ = __ldg(&anc[2 * a_ + 1]);
    }

    // ====== GT preprocessing: warp 0 only, ONE barrier ======
    if (wid == 0) {
        const float* tb = tgt + b * MAXGT * 5;
        float a1 = tb[lane * 5 + 1];
        float a2 = tb[lane * 5 + 2];
        float a3 = tb[lane * 5 + 3];
        float a4 = tb[lane * 5 + 4];
        bool vA = (a1 > 0.0f);
        float c1 = 0.f, c2 = 0.f, c3 = 0.f, c4 = 0.f;
        bool vB = false;
        if (lane < MAXGT - 32) {
            int s = 32 + lane;
            c1 = tb[s * 5 + 1]; c2 = tb[s * 5 + 2];
            c3 = tb[s * 5 + 3]; c4 = tb[s * 5 + 4];
            vB = (c1 > 0.0f);
        }
        unsigned mA = __ballot_sync(0xffffffffu, vA);
        unsigned mB = __ballot_sync(0xffffffffu, vB);
        int cA = __popc(mA);
        if (vA) {
            int idx = __popc(mA & ((1u << lane) - 1u));
            float gx = a1 * NW, gy = a2 * NH, gw = a3 * NW, gh = a4 * NH;
            sboxv[idx] = make_float4(gx - gw * 0.5f, gy - gh * 0.5f,
                                     gx + gw * 0.5f, gy + gh * 0.5f);
            sb6[idx] = SIL_T * (gw * gh);
        }
        if (vB) {
            int idx = cA + __popc(mB & ((1u << lane) - 1u));
            float gx = c1 * NW, gy = c2 * NH, gw = c3 * NW, gh = c4 * NH;
            sboxv[idx] = make_float4(gx - gw * 0.5f, gy - gh * 0.5f,
                                     gx + gw * 0.5f, gy + gh * 0.5f);
            sb6[idx] = SIL_T * (gw * gh);
        }
        if (lane == 0) scnt = cA + __popc(mB);
    }
    __syncthreads();
    const int cnt = scnt;

    float local = 0.0f;

    if (cellBlock) {
        const float fj = (float)j_;

        float xs[4] = {sigm_fast(L0.x), sigm_fast(L0.y), sigm_fast(L0.z), sigm_fast(L0.w)};
        float ys[4] = {sigm_fast(L1.x), sigm_fast(L1.y), sigm_fast(L1.z), sigm_fast(L1.w)};
        float ws[4] = {L2.x, L2.y, L2.z, L2.w};
        float hs[4] = {L3.x, L3.y, L3.z, L3.w};
        float cs[4] = {sigm_fast(L4.x), sigm_fast(L4.y), sigm_fast(L4.z), sigm_fast(L4.w)};

        float px1[4], py1[4], px2[4], py2[4], p6[4], mi[4];
        #pragma unroll
        for (int c = 0; c < 4; ++c) {
            float px = xs[c] + (float)(i0_ + c);
            float py = ys[c] + fj;
            float pw = __expf(ws[c]) * aw_;
            float ph = __expf(hs[c]) * ah_;
            px1[c] = px - pw * 0.5f; py1[c] = py - ph * 0.5f;
            px2[c] = px + pw * 0.5f; py2[c] = py + ph * 0.5f;
            p6[c]  = SIL_T * (pw * ph);
            mi[c]  = -1e30f;          // running max of 1.6*inter - 0.6*barea
        }

        // ---- branchless warp-level y-cull ----
        // A GT box with no y-overlap contributes (−b6) < 0 < p6 to mi —
        // provably a no-op — so build a warp-uniform bitmask of overlapping
        // boxes once and iterate only over its set bits.
        float wymin = fminf(fminf(py1[0], py1[1]), fminf(py1[2], py1[3]));
        float wymax = fmaxf(fmaxf(py2[0], py2[1]), fmaxf(py2[2], py2[3]));
        #pragma unroll
        for (int off = 16; off > 0; off >>= 1) {
            wymin = fminf(wymin, __shfl_xor_sync(0xffffffffu, wymin, off));
            wymax = fmaxf(wymax, __shfl_xor_sync(0xffffffffu, wymax, off));
        }
        bool ovA = false, ovB = false;
        if (lane < cnt) {
            float4 bv = sboxv[lane];
            ovA = (bv.w >= wymin) && (bv.y <= wymax);
        }
        if (32 + lane < cnt) {
            float4 bv = sboxv[32 + lane];
            ovB = (bv.w >= wymin) && (bv.y <= wymax);
        }
        unsigned m0 = __ballot_sync(0xffffffffu, ovA);
        unsigned m1 = __ballot_sync(0xffffffffu, ovB);

        #pragma unroll 1
        for (unsigned m = m0; m; m &= m - 1u) {
            int g = __ffs(m) - 1;
            float4 bv = sboxv[g];
            float b6 = sb6[g];
            #pragma unroll
            for (int c = 0; c < 4; ++c) {
                float iw = fmaxf(fminf(px2[c], bv.z) - fmaxf(px1[c], bv.x), 0.0f);
                float ih = fmaxf(fminf(py2[c], bv.w) - fmaxf(py1[c], bv.y), 0.0f);
                mi[c] = fmaxf(mi[c], fmaf((1.0f + SIL_T), iw * ih, -b6));
            }
        }
        #pragma unroll 1
        for (unsigned m = m1; m; m &= m - 1u) {
            int g = 32 + __ffs(m) - 1;
            float4 bv = sboxv[g];
            float b6 = sb6[g];
            #pragma unroll
            for (int c = 0; c < 4; ++c) {
                float iw = fmaxf(fminf(px2[c], bv.z) - fmaxf(px1[c], bv.x), 0.0f);
                float ih = fmaxf(fminf(py2[c], bv.w) - fmaxf(py1[c], bv.y), 0.0f);
                mi[c] = fmaxf(mi[c], fmaf((1.0f + SIL_T), iw * ih, -b6));
            }
        }

        #pragma unroll
        for (int c = 0; c < 4; ++c) {
            float dx = xs[c] - 0.5f, dy = ys[c] - 0.5f;
            float cmb = (mi[c] > p6[c]) ? 0.0f : 1.0f;
            local += 0.5f * (dx * dx + dy * dy + ws[c] * ws[c] + hs[c] * hs[c])
                   + 0.5f * cmb * cs[c] * cs[c];
        }
    } else {
        // ---- per-GT correction terms (one thread per GT slot) ----
        int best = 0;
        float txv = 0.f, tyv = 0.f, twv = 0.f, thv = 0.f;
        int tcls = 0;
        bool valid = false;
        float gx = 0.f, gy = 0.f, gw = 0.f, gh = 0.f;

        if (tid < MAXGT) {
            const float* t = tgt + (b * MAXGT + tid) * 5;
            float t0 = t[0], t1 = t[1], t2 = t[2], t3 = t[3], t4 = t[4];
            valid = (t1 > 0.0f);
            if (valid) {
                gx = t1 * NW; gy = t2 * NH; gw = t3 * NW; gh = t4 * NH;
                float bestiou = -1.0f;
                for (int a = 0; a < NA; ++a) {
                    float aw = __ldg(&anc[2 * a]), ah = __ldg(&anc[2 * a + 1]);
                    float inter = fminf(gw, aw) * fminf(gh, ah);
                    float uni = gw * gh + aw * ah - inter;
                    float io = uni > 0.0f ? inter / uni : 0.0f;
                    if (io > bestiou) { bestiou = io; best = a; }
                }
                int gi = min(max((int)gx, 0), NW - 1);
                int gj = min(max((int)gy, 0), NH - 1);
                sflat[tid] = ((b * NA + best) * NH + gj) * NW + gi;
                float aw = __ldg(&anc[2 * best]), ah = __ldg(&anc[2 * best + 1]);
                txv = gx - (float)gi;
                tyv = gy - (float)gj;
                twv = logf(fmaxf(gw, 1e-12f) / aw);
                thv = logf(fmaxf(gh, 1e-12f) / ah);
                tcls = (int)t0;
            } else {
                sflat[tid] = -1;
            }
        }
        __syncthreads();   // GT block only: sflat visibility across warps

        if (tid < MAXGT && valid) {
            // last-write-wins: skip if a later valid GT writes the same cell
            bool skip = false;
            int myflat = sflat[tid];
            for (int g2 = tid + 1; g2 < MAXGT; ++g2)
                if (sflat[g2] == myflat) skip = true;

            if (!skip) {
                int i = myflat & 63;
                int j = (myflat >> 6) & 63;
                int a = best;
                int base = ((b * CH + a * (5 + NCLS)) * NH + j) * NW + i;

                float o0 = out[base];
                float o1 = out[base + SPLANE];
                float o2 = out[base + 2 * SPLANE];
                float o3 = out[base + 3 * SPLANE];
                float o4 = out[base + 4 * SPLANE];
                float x = sigm(o0), y = sigm(o1), w = o2, h = o3, conf = sigm(o4);

                float aw = __ldg(&anc[2 * a]), ah = __ldg(&anc[2 * a + 1]);
                float px = x + (float)i, py = y + (float)j;
                float pw = expf(w) * aw, ph = expf(h) * ah;
                float px1 = px - pw * 0.5f, py1 = py - ph * 0.5f;
                float px2 = px + pw * 0.5f, py2 = py + ph * 0.5f;
                float parea = pw * ph;
                float p6 = SIL_T * parea;

                bool over = false;
                for (int g = 0; g < cnt; ++g) {
                    float4 bv = sboxv[g];
                    float iw = fmaxf(fminf(px2, bv.z) - fmaxf(px1, bv.x), 0.0f);
                    float ih = fmaxf(fminf(py2, bv.w) - fmaxf(py1, bv.y), 0.0f);
                    over |= (1.0f + SIL_T) * (iw * ih) > (p6 + sb6[g]);
                }
                float cmb = over ? 0.0f : 1.0f;

                // iou of predicted box at this cell vs THIS gt box (precise)
                float iou_best = iou_corners(px1, py1, px2, py2, parea,
                                             gx - gw * 0.5f, gy - gh * 0.5f,
                                             gx + gw * 0.5f, gy + gh * 0.5f, gw * gh);

                float d = 0.0f, e;
                e = x - txv;       d += 0.5f * e * e;
                e = x - 0.5f;      d -= 0.5f * e * e;
                e = y - tyv;       d += 0.5f * e * e;
                e = y - 0.5f;      d -= 0.5f * e * e;
                e = w - twv;       d += 0.5f * e * e;  d -= 0.5f * w * w;
                e = h - thv;       d += 0.5f * e * e;  d -= 0.5f * h * h;
                e = conf - iou_best; d += 0.5f * 5.0f * e * e;
                d -= 0.5f * cmb * conf * conf;

                // class NLL
                float mx = -1e30f;
                #pragma unroll
                for (int c = 0; c < NCLS; ++c)
                    mx = fmaxf(mx, out[base + (5 + c) * SPLANE]);
                float s = 0.0f;
                #pragma unroll
                for (int c = 0; c < NCLS; ++c)
                    s += expf(out[base + (5 + c) * SPLANE] - mx);
                d += mx + logf(s) - out[base + (5 + tcls) * SPLANE];

                local = d;
            }
        }
    }

    // ---- block reduction (float), then one double atomic per block,
    //      spread over NSLOT accumulator slots to avoid same-address
    //      serialization at the LTS atomic ALU ----
    for (int off = 16; off > 0; off >>= 1)
        local += __shfl_down_sync(0xffffffffu, local, off);
    if (lane == 0) ssum[wid] = local;
    __syncthreads();
    if (tid == 0) {
        float v = ssum[0];
        #pragma unroll
        for (int k = 1; k < NWARPS; ++k) v += ssum[k];
        int blin = b * BXDIM + bx;
        atomicAdd(&g_slot[blin & (NSLOT - 1)], (double)v);
        __threadfence();
        unsigned c = atomicAdd(&g_counter, 1u);
        if (c == NBLOCKS - 1) {
            __threadfence();
            double total = 0.0;
            #pragma unroll
            for (int k = 0; k < NSLOT; ++k) {
                total += *((volatile double*)&g_slot[k]);
                g_slot[k] = 0.0;      // reset for next graph replay
            }
            res[0] = (float)total;
            g_counter = 0;
        }
    }
}

extern "C" void kernel_launch(void* const* d_in, const int* in_sizes, int n_in,
                              void* d_out, int out_size) {
    const float* out = (const float*)d_in[0];
    const float* tgt = (const float*)d_in[1];
    const float* anc = (const float*)d_in[2];

    dim3 grid(BXDIM, NB);
    yolo_fused<<<grid, TPB>>>(out, tgt, anc, (float*)d_out);
}